// round 16
// baseline (speedup 1.0000x reference)
#include <cuda_runtime.h>
#include <cstdint>

#define TT 128
#define BB 512
#define EE 128
#define NEVT 16
#define NBC 16              // batches per CTA (2 groups of 8)
#define NBLK (BB / NBC)     // 32 CTAs
#define L2E 1.4426950408889634f
#define LN2 0.6931471805599453f
#define NEGL2 (-10000.0f * L2E)

__device__ float g_partial[BB];
__device__ unsigned g_done;     // zero-init; restored each launch

// ---------------------------------------------------------------------------
__device__ __forceinline__ float ex2(float x) {
    float r; asm("ex2.approx.ftz.f32 %0, %1;" : "=f"(r) : "f"(x)); return r;
}
__device__ __forceinline__ float lg2(float x) {
    float r; asm("lg2.approx.ftz.f32 %0, %1;" : "=f"(r) : "f"(x)); return r;
}
__device__ __forceinline__ uint32_t packbf(float lo, float hi) {   // {hi:lo}
    uint32_t r;
    asm("cvt.rn.satfinite.bf16x2.f32 %0, %1, %2;" : "=r"(r) : "f"(hi), "f"(lo));
    return r;
}
__device__ __forceinline__ void mma16(float& c0, float& c1, float& c2, float& c3,
                                      uint32_t a0, uint32_t a1, uint32_t a2,
                                      uint32_t a3, uint32_t b0, uint32_t b1) {
    asm volatile(
        "mma.sync.aligned.m16n8k16.row.col.f32.bf16.bf16.f32 "
        "{%0,%1,%2,%3}, {%4,%5,%6,%7}, {%8,%9}, {%0,%1,%2,%3};"
        : "+f"(c0), "+f"(c1), "+f"(c2), "+f"(c3)
        : "r"(a0), "r"(a1), "r"(a2), "r"(a3), "r"(b0), "r"(b1));
}
// group-scoped barrier: group gi (256 threads) syncs on named barrier gi+1
__device__ __forceinline__ void gbar(int gi) {
    asm volatile("bar.sync %0, 256;" :: "r"(gi + 1) : "memory");
}

// ---------------------------------------------------------------------------
// R15 bf16 HMMA kernel x 2 INDEPENDENT batch-groups per 512-thread CTA.
// Each group of 8 warps runs the R15 step loop on its own P buffer and its
// own NAMED barrier (bar.sync gi+1, 256) — no CTA-wide lockstep, so the two
// groups drift and hide each other's LDS/HMMA/MUFU latency (R15 measured all
// pipes >=75% idle at 2 warps/SMSP; R13's failure was tf32 2x traffic plus a
// shared __syncthreads coupling the groups).
// Per group: warp lw owns rows 16lw..16lw+15, cols = 8 batches, Q stationary
// in bf16 A-fragments, 8 chained m16n8k16 MMAs/step, P as bf16x2 j-pairs.
// Normalizer G(b) = fv[row 17][b] lagged 2 steps (3-slot rotation).
// ---------------------------------------------------------------------------
__global__ void __launch_bounds__(512)
crf_kernel(const float* __restrict__ feats, const float* __restrict__ trans,
           float* __restrict__ out, int nblocks) {
    const int tid = threadIdx.x;
    const int w = tid >> 5, lane = tid & 31;
    const int gi = w >> 3, lw = w & 7;          // group, warp-in-group
    const int g = lane >> 2, tig = lane & 3;
    const int r0 = 16 * lw + g, r1 = r0 + 8;
    const int bA = 2 * tig, bB = bA + 1;
    const int b0g = blockIdx.x * NBC + gi * 8;

    __shared__ __align__(16) uint32_t P2[2][2][512];  // [group][parity][(j>>1)*8+b]
    __shared__ float slot[2][3][8];
    __shared__ float bwp[2][NEVT][8][8];
    __shared__ float gsv[2][NEVT][8];
    __shared__ float mt2s[EE], tl2s[EE];
    __shared__ float rsum[16];
    __shared__ unsigned slast;

    // ---- feat prefetch pointers: (r0,bA),(r0,bB),(r1,bA),(r1,bB) ----
    const size_t tstr = (size_t)BB * EE;
    const float* fpp[4];
    fpp[0] = feats + (size_t)(b0g + bA) * EE + r0;
    fpp[1] = feats + (size_t)(b0g + bB) * EE + r0;
    fpp[2] = fpp[0] + 8;
    fpp[3] = fpp[1] + 8;
    float f1[4], fcur[4], fnx[4], fnew[4];
#pragma unroll
    for (int i = 0; i < 4; i++) f1[i]   = fpp[i][tstr];
#pragma unroll
    for (int i = 0; i < 4; i++) fcur[i] = fpp[i][2 * tstr];
#pragma unroll
    for (int i = 0; i < 4; i++) fnx[i]  = fpp[i][3 * tstr];
#pragma unroll
    for (int i = 0; i < 4; i++) fnew[i] = fnx[i];

    // ---- row maxes + last-row transitions (log2 units) ----
    if (tid < EE) {
        const float4* rp = (const float4*)(trans + tid * EE);
        float m = -3.4e38f;
#pragma unroll
        for (int i = 0; i < 32; i++) {
            float4 v = rp[i];
            m = fmaxf(m, fmaxf(fmaxf(v.x, v.y), fmaxf(v.z, v.w)));
        }
        mt2s[tid] = m * L2E;
        tl2s[tid] = trans[(EE - 1) * EE + tid] * L2E;
    }
    if (tid < 16)       // preinit G slot[2] for both groups
        slot[tid >> 3][2][tid & 7] =
            (blockIdx.x * NBC + tid == 0) ? 0.0f : NEGL2;
    __syncthreads();

    const float mtA = mt2s[r0], mtB = mt2s[r1];
    const float etlA = ex2(mtA + tl2s[r0]);
    const float etlB = ex2(mtB + tl2s[r1]);

    // ---- stationary A fragments (bf16): Q rows r0,r1, K-chunks of 16 ----
    uint32_t a[8][4];
#pragma unroll
    for (int s = 0; s < 8; s++) {
        int k0 = 16 * s + 2 * tig;
        float qA0 = ex2(fmaf(trans[r0 * EE + k0],     L2E, -mtA));
        float qA1 = ex2(fmaf(trans[r0 * EE + k0 + 1], L2E, -mtA));
        float qB0 = ex2(fmaf(trans[r1 * EE + k0],     L2E, -mtB));
        float qB1 = ex2(fmaf(trans[r1 * EE + k0 + 1], L2E, -mtB));
        float qA8 = ex2(fmaf(trans[r0 * EE + k0 + 8], L2E, -mtA));
        float qA9 = ex2(fmaf(trans[r0 * EE + k0 + 9], L2E, -mtA));
        float qB8 = ex2(fmaf(trans[r1 * EE + k0 + 8], L2E, -mtB));
        float qB9 = ex2(fmaf(trans[r1 * EE + k0 + 9], L2E, -mtB));
        a[s][0] = packbf(qA0, qA1);
        a[s][1] = packbf(qB0, qB1);
        a[s][2] = packbf(qA8, qA9);
        a[s][3] = packbf(qB8, qB9);
    }

    float Gc[2];
    Gc[0] = (b0g + bA == 0) ? 0.0f : NEGL2;
    Gc[1] = NEGL2;                      // b0g + bB >= 1 always

    // ---- P_0 = 2^(f(t=1)*L2E), packed bf16x2 over j-pairs ----
    {
        float p0 = ex2(f1[0] * L2E), p1 = ex2(f1[1] * L2E);
        float p2 = ex2(f1[2] * L2E), p3 = ex2(f1[3] * L2E);
        float q0 = __shfl_xor_sync(0xffffffffu, p0, 4);
        float q1 = __shfl_xor_sync(0xffffffffu, p1, 4);
        float q2 = __shfl_xor_sync(0xffffffffu, p2, 4);
        float q3 = __shfl_xor_sync(0xffffffffu, p3, 4);
        if (!(lane & 4)) {
            *(uint2*)&P2[gi][0][(r0 >> 1) * 8 + bA] =
                make_uint2(packbf(p0, q0), packbf(p1, q1));
            *(uint2*)&P2[gi][0][(r1 >> 1) * 8 + bA] =
                make_uint2(packbf(p2, q2), packbf(p3, q3));
        }
    }
    __syncthreads();    // last CTA-wide barrier; loop uses group barriers

#pragma unroll 1
    for (int u = 0; u < 112; u++) {
        // ---- front-batched B-fragment loads: 16x LDS.32, conflict-free ----
        const uint32_t* PB = P2[gi][u & 1];
        uint32_t bv0[8], bv1[8];
#pragma unroll
        for (int s = 0; s < 8; s++) {
            bv0[s] = PB[64 * s + 8 * tig + g];
            bv1[s] = PB[64 * s + 32 + 8 * tig + g];
        }

        // ---- shadow: normalizer + ec for P_{u+1}, feat prefetch ----
        const int ri = (u + 2) % 3;
        float Gn0 = slot[gi][ri][bA], Gn1 = slot[gi][ri][bB];
        float ec[4];
        ec[0] = ex2(fmaf(fcur[0], L2E, Gc[0] + mtA - Gn0));
        ec[1] = ex2(fmaf(fcur[1], L2E, Gc[1] + mtA - Gn1));
        ec[2] = ex2(fmaf(fcur[2], L2E, Gc[0] + mtB - Gn0));
        ec[3] = ex2(fmaf(fcur[3], L2E, Gc[1] + mtB - Gn1));
        if (u <= 108) {
            size_t off = (size_t)(u + 4 + (u + 3) / 7) * tstr;   // t(u+3)
#pragma unroll
            for (int i = 0; i < 4; i++) fnew[i] = fpp[i][off];
        }

        // ---- tensor matvec: 8 HMMA, 4 chains x 2 deep ----
        float c[4][4];
#pragma unroll
        for (int qq = 0; qq < 4; qq++)
#pragma unroll
            for (int i = 0; i < 4; i++) c[qq][i] = 0.0f;
#pragma unroll
        for (int s = 0; s < 8; s++) {
            mma16(c[s & 3][0], c[s & 3][1], c[s & 3][2], c[s & 3][3],
                  a[s][0], a[s][1], a[s][2], a[s][3], bv0[s], bv1[s]);
        }
        float y0 = (c[0][0] + c[1][0]) + (c[2][0] + c[3][0]);  // (r0,bA)
        float y1 = (c[0][1] + c[1][1]) + (c[2][1] + c[3][1]);  // (r0,bB)
        float y2 = (c[0][2] + c[1][2]) + (c[2][2] + c[3][2]);  // (r1,bA)
        float y3 = (c[0][3] + c[1][3]) + (c[2][3] + c[3][3]);  // (r1,bB)

        // ---- P_{u+1} = y * ec (bf16x2 pack over j-pairs) ----
        if (u < 111) {
            float p0 = y0 * ec[0], p1 = y1 * ec[1];
            float p2 = y2 * ec[2], p3 = y3 * ec[3];
            float q0 = __shfl_xor_sync(0xffffffffu, p0, 4);
            float q1 = __shfl_xor_sync(0xffffffffu, p1, 4);
            float q2 = __shfl_xor_sync(0xffffffffu, p2, 4);
            float q3 = __shfl_xor_sync(0xffffffffu, p3, 4);
            if (!(lane & 4)) {
                uint32_t* PW = P2[gi][(u + 1) & 1];
                *(uint2*)&PW[(r0 >> 1) * 8 + bA] =
                    make_uint2(packbf(p0, q0), packbf(p1, q1));
                *(uint2*)&PW[(r1 >> 1) * 8 + bA] =
                    make_uint2(packbf(p2, q2), packbf(p3, q3));
            }
        }

        // ---- publish G (row 17 = lw 1, g==1, r0 path) per group ----
        if (lw == 1 && g == 1) {
            slot[gi][u % 3][bA] = Gc[0] + mtA + lg2(y0);
            slot[gi][u % 3][bB] = Gc[1] + mtA + lg2(y1);
        }

        // ---- boundary lse partials (every 7th step, e = u/7) ----
        if ((u % 7) == 6) {
            int e = u / 7;
            float sA = fmaf(y0, etlA, y2 * etlB);
            float sB = fmaf(y1, etlA, y3 * etlB);
            sA += __shfl_xor_sync(0xffffffffu, sA, 4);
            sB += __shfl_xor_sync(0xffffffffu, sB, 4);
            sA += __shfl_xor_sync(0xffffffffu, sA, 8);
            sB += __shfl_xor_sync(0xffffffffu, sB, 8);
            sA += __shfl_xor_sync(0xffffffffu, sA, 16);
            sB += __shfl_xor_sync(0xffffffffu, sB, 16);
            if (lane < 4) {
                bwp[gi][e][lw][bA] = sA;
                bwp[gi][e][lw][bB] = sB;
                if (lw == 0) { gsv[gi][e][bA] = Gc[0]; gsv[gi][e][bB] = Gc[1]; }
            }
        }

        gbar(gi);       // group-scoped barrier: groups drift independently
        Gc[0] = Gn0; Gc[1] = Gn1;
#pragma unroll
        for (int i = 0; i < 4; i++) { fcur[i] = fnx[i]; fnx[i] = fnew[i]; }
    }

    __syncthreads();    // rejoin groups before combine

    // ---- combine 16 events x 16 batches ----
    if (tid < 256) {
        int e = tid & 15, bb = tid >> 4;
        int gg = bb >> 3, b = bb & 7;
        float s8 = 0.0f;
#pragma unroll
        for (int ww = 0; ww < 8; ww++) s8 += bwp[gg][e][ww][b];
        float val = gsv[gg][e][b] + lg2(s8);
#pragma unroll
        for (int o = 1; o < 16; o <<= 1)
            val += __shfl_xor_sync(0xffffffffu, val, o);
        if (e == 0) g_partial[blockIdx.x * NBC + bb] = val * LN2;
    }

    // ---- fused final reduction (last CTA of 32) ----
    __threadfence();
    __syncthreads();
    if (tid == 0) {
        unsigned v = atomicAdd(&g_done, 1u);
        slast = (v == (unsigned)(nblocks - 1)) ? 1u : 0u;
    }
    __syncthreads();
    if (slast) {
        __threadfence();
        float v = __ldcg(&g_partial[tid]);      // 512 threads = 512 partials
#pragma unroll
        for (int o = 16; o; o >>= 1) v += __shfl_xor_sync(0xffffffffu, v, o);
        if (lane == 0) rsum[w] = v;
        __syncthreads();
        if (tid == 0) {
            float tot = 0.0f;
#pragma unroll
            for (int ww = 0; ww < 16; ww++) tot += rsum[ww];
            out[0] = tot * (1.0f / (float)(BB * NEVT));
            g_done = 0;                         // restore for next graph replay
        }
    }
}

// ---------------------------------------------------------------------------
extern "C" void kernel_launch(void* const* d_in, const int* in_sizes, int n_in,
                              void* d_out, int out_size) {
    const float* feats = (const float*)d_in[0];
    const float* trans = (const float*)d_in[1];
    if (n_in >= 2 && in_sizes[0] == EE * EE) {   // defensive order check
        feats = (const float*)d_in[1];
        trans = (const float*)d_in[0];
    }
    crf_kernel<<<NBLK, 512>>>(feats, trans, (float*)d_out, NBLK);
}

// round 17
// speedup vs baseline: 1.2536x; 1.2536x over previous
#include <cuda_runtime.h>
#include <cuda_bf16.h>
#include <cstdint>

#define TT 128
#define BB 512
#define EE 128
#define NEVT 16
#define NBC 8               // batches per CTA
#define NBLK (BB / NBC)     // 64 CTAs
#define L2E 1.4426950408889634f
#define LN2 0.6931471805599453f
#define NEGL2 (-10000.0f * L2E)

__device__ float g_partial[BB];
__device__ unsigned g_done;     // zero-init; restored each launch

// ---------------------------------------------------------------------------
__device__ __forceinline__ float ex2(float x) {
    float r; asm("ex2.approx.ftz.f32 %0, %1;" : "=f"(r) : "f"(x)); return r;
}
__device__ __forceinline__ float lg2(float x) {
    float r; asm("lg2.approx.ftz.f32 %0, %1;" : "=f"(r) : "f"(x)); return r;
}
__device__ __forceinline__ uint32_t packbf(float lo, float hi) {   // {hi:lo}
    uint32_t r;
    asm("cvt.rn.satfinite.bf16x2.f32 %0, %1, %2;" : "=r"(r) : "f"(hi), "f"(lo));
    return r;
}
__device__ __forceinline__ void mma16(float& c0, float& c1, float& c2, float& c3,
                                      uint32_t a0, uint32_t a1, uint32_t a2,
                                      uint32_t a3, uint32_t b0, uint32_t b1) {
    asm volatile(
        "mma.sync.aligned.m16n8k16.row.col.f32.bf16.bf16.f32 "
        "{%0,%1,%2,%3}, {%4,%5,%6,%7}, {%8,%9}, {%0,%1,%2,%3};"
        : "+f"(c0), "+f"(c1), "+f"(c2), "+f"(c3)
        : "r"(a0), "r"(a1), "r"(a2), "r"(a3), "r"(b0), "r"(b1));
}

// ---------------------------------------------------------------------------
// R15 winner (64 CTAs x 256 threads; warp w rows 16w..16w+15, cols = 8
// batches; Q stationary in bf16 A-fragments; 8 chained m16n8k16 MMAs/step;
// P as bf16x2 j-pairs in smem) with three critical-path cuts:
//   1. MMAs issued IMMEDIATELY after B loads; shadow work (normalizer LDS,
//      ec ex2, feat LDG, deferred boundary) runs while the HMMA chain is in
//      flight, before y is consumed.
//   2. P written via 4x st.shared.u16 of own bf16 values (no SHFL/pack on
//      the post-MMA tail). Reader layout identical.
//   3. Boundary lse shuffle-reduces deferred one step into the shadow slot
//      (y/Gc saved in regs; terminal event processed after the loop).
// Normalizer G(b) = fv[row 17][b] lagged 2 steps (3-slot rotation).
// ---------------------------------------------------------------------------
__global__ void __launch_bounds__(256)
crf_kernel(const float* __restrict__ feats, const float* __restrict__ trans,
           float* __restrict__ out, int nblocks) {
    const int tid = threadIdx.x;
    const int w = tid >> 5, lane = tid & 31;
    const int g = lane >> 2, tig = lane & 3;
    const int r0 = 16 * w + g, r1 = r0 + 8;
    const int bA = 2 * tig, bB = bA + 1;
    const int b0 = blockIdx.x * NBC;

    __shared__ __align__(16) uint32_t P2[2][512];   // [parity][(j>>1)*8 + b]
    __shared__ float slot[3][NBC];                  // G rotation
    __shared__ float bwp[NEVT][8][NBC];             // boundary partials
    __shared__ float gsv[NEVT][NBC];                // Gc at each event
    __shared__ float mt2s[EE], tl2s[EE];
    __shared__ float rsum[8];
    __shared__ unsigned slast;

    // ---- feat prefetch pointers: (r0,bA),(r0,bB),(r1,bA),(r1,bB) ----
    const size_t tstr = (size_t)BB * EE;
    const float* fpp[4];
    fpp[0] = feats + (size_t)(b0 + bA) * EE + r0;
    fpp[1] = feats + (size_t)(b0 + bB) * EE + r0;
    fpp[2] = fpp[0] + 8;
    fpp[3] = fpp[1] + 8;
    float f1[4], fcur[4], fnx[4], fnew[4];
#pragma unroll
    for (int i = 0; i < 4; i++) f1[i]   = fpp[i][tstr];
#pragma unroll
    for (int i = 0; i < 4; i++) fcur[i] = fpp[i][2 * tstr];
#pragma unroll
    for (int i = 0; i < 4; i++) fnx[i]  = fpp[i][3 * tstr];
#pragma unroll
    for (int i = 0; i < 4; i++) fnew[i] = fnx[i];

    // ---- row maxes + last-row transitions (log2 units) ----
    if (tid < EE) {
        const float4* rp = (const float4*)(trans + tid * EE);
        float m = -3.4e38f;
#pragma unroll
        for (int i = 0; i < 32; i++) {
            float4 v = rp[i];
            m = fmaxf(m, fmaxf(fmaxf(v.x, v.y), fmaxf(v.z, v.w)));
        }
        mt2s[tid] = m * L2E;
        tl2s[tid] = trans[(EE - 1) * EE + tid] * L2E;
    }
    if (tid < NBC)      // preinit G slot[2] (= G_1 = fv_init)
        slot[2][tid] = (b0 + tid == 0) ? 0.0f : NEGL2;
    __syncthreads();

    const float mtA = mt2s[r0], mtB = mt2s[r1];
    const float etlA = ex2(mtA + tl2s[r0]);
    const float etlB = ex2(mtB + tl2s[r1]);

    // ---- stationary A fragments (bf16): Q rows r0,r1, K-chunks of 16 ----
    uint32_t a[8][4];
#pragma unroll
    for (int s = 0; s < 8; s++) {
        int k0 = 16 * s + 2 * tig;
        float qA0 = ex2(fmaf(trans[r0 * EE + k0],     L2E, -mtA));
        float qA1 = ex2(fmaf(trans[r0 * EE + k0 + 1], L2E, -mtA));
        float qB0 = ex2(fmaf(trans[r1 * EE + k0],     L2E, -mtB));
        float qB1 = ex2(fmaf(trans[r1 * EE + k0 + 1], L2E, -mtB));
        float qA8 = ex2(fmaf(trans[r0 * EE + k0 + 8], L2E, -mtA));
        float qA9 = ex2(fmaf(trans[r0 * EE + k0 + 9], L2E, -mtA));
        float qB8 = ex2(fmaf(trans[r1 * EE + k0 + 8], L2E, -mtB));
        float qB9 = ex2(fmaf(trans[r1 * EE + k0 + 9], L2E, -mtB));
        a[s][0] = packbf(qA0, qA1);
        a[s][1] = packbf(qB0, qB1);
        a[s][2] = packbf(qA8, qA9);
        a[s][3] = packbf(qB8, qB9);
    }

    float Gc[2];
    Gc[0] = (b0 + bA == 0) ? 0.0f : NEGL2;
    Gc[1] = NEGL2;                      // b0 + bB >= 1 always

    // bf16 halfword store addresses (byte offsets within a parity buffer):
    //   word (j>>1)*8 + b, halfword (j&1)*2
    __nv_bfloat16* const Pbf0 = (__nv_bfloat16*)&P2[0][0];
    __nv_bfloat16* const Pbf1 = (__nv_bfloat16*)&P2[1][0];
    const int h0A = ((r0 >> 1) * 8 + bA) * 2 + (r0 & 1);
    const int h0B = ((r0 >> 1) * 8 + bB) * 2 + (r0 & 1);
    const int h1A = ((r1 >> 1) * 8 + bA) * 2 + (r1 & 1);
    const int h1B = ((r1 >> 1) * 8 + bB) * 2 + (r1 & 1);

    // ---- P_0 = 2^(f(t=1)*L2E) ----
    Pbf0[h0A] = __float2bfloat16(ex2(f1[0] * L2E));
    Pbf0[h0B] = __float2bfloat16(ex2(f1[1] * L2E));
    Pbf0[h1A] = __float2bfloat16(ex2(f1[2] * L2E));
    Pbf0[h1B] = __float2bfloat16(ex2(f1[3] * L2E));
    __syncthreads();

    float py[4] = {0, 0, 0, 0};        // deferred boundary y's
    float pG[2] = {0, 0};              // deferred boundary Gc's

#pragma unroll 1
    for (int u = 0; u < 112; u++) {
        // ---- B-fragment loads: 16x LDS.32, conflict-free ----
        const uint32_t* PB = P2[u & 1];
        uint32_t bv0[8], bv1[8];
#pragma unroll
        for (int s = 0; s < 8; s++) {
            bv0[s] = PB[64 * s + 8 * tig + g];
            bv1[s] = PB[64 * s + 32 + 8 * tig + g];
        }

        // ---- MMAs issued immediately: 8 HMMA, 4 chains x 2 deep ----
        float c[4][4];
#pragma unroll
        for (int qq = 0; qq < 4; qq++)
#pragma unroll
            for (int i = 0; i < 4; i++) c[qq][i] = 0.0f;
#pragma unroll
        for (int s = 0; s < 8; s++) {
            mma16(c[s & 3][0], c[s & 3][1], c[s & 3][2], c[s & 3][3],
                  a[s][0], a[s][1], a[s][2], a[s][3], bv0[s], bv1[s]);
        }

        // ---- shadow (runs while HMMA chain is in flight) ----
        const int ri = (u + 2) % 3;
        float Gn0 = slot[ri][bA], Gn1 = slot[ri][bB];
        if (u <= 108) {
            size_t off = (size_t)(u + 4 + (u + 3) / 7) * tstr;   // t(u+3)
#pragma unroll
            for (int i = 0; i < 4; i++) fnew[i] = fpp[i][off];
        }
        float ec[4];
        ec[0] = ex2(fmaf(fcur[0], L2E, Gc[0] + mtA - Gn0));
        ec[1] = ex2(fmaf(fcur[1], L2E, Gc[1] + mtA - Gn1));
        ec[2] = ex2(fmaf(fcur[2], L2E, Gc[0] + mtB - Gn0));
        ec[3] = ex2(fmaf(fcur[3], L2E, Gc[1] + mtB - Gn1));
        if (u >= 7 && (u % 7) == 0) {      // deferred boundary e = u/7 - 1
            int e = u / 7 - 1;
            float sA = fmaf(py[0], etlA, py[2] * etlB);
            float sB = fmaf(py[1], etlA, py[3] * etlB);
            sA += __shfl_xor_sync(0xffffffffu, sA, 4);
            sB += __shfl_xor_sync(0xffffffffu, sB, 4);
            sA += __shfl_xor_sync(0xffffffffu, sA, 8);
            sB += __shfl_xor_sync(0xffffffffu, sB, 8);
            sA += __shfl_xor_sync(0xffffffffu, sA, 16);
            sB += __shfl_xor_sync(0xffffffffu, sB, 16);
            if (lane < 4) {
                bwp[e][w][bA] = sA;
                bwp[e][w][bB] = sB;
                if (w == 0) { gsv[e][bA] = pG[0]; gsv[e][bB] = pG[1]; }
            }
        }

        // ---- consume y ----
        float y0 = (c[0][0] + c[1][0]) + (c[2][0] + c[3][0]);  // (r0,bA)
        float y1 = (c[0][1] + c[1][1]) + (c[2][1] + c[3][1]);  // (r0,bB)
        float y2 = (c[0][2] + c[1][2]) + (c[2][2] + c[3][2]);  // (r1,bA)
        float y3 = (c[0][3] + c[1][3]) + (c[2][3] + c[3][3]);  // (r1,bB)

        // ---- P_{u+1} = y * ec: 4x st.shared.u16 (no shuffles) ----
        if (u < 111) {
            __nv_bfloat16* PW = ((u + 1) & 1) ? Pbf1 : Pbf0;
            PW[h0A] = __float2bfloat16(y0 * ec[0]);
            PW[h0B] = __float2bfloat16(y1 * ec[1]);
            PW[h1A] = __float2bfloat16(y2 * ec[2]);
            PW[h1B] = __float2bfloat16(y3 * ec[3]);
        }

        // ---- publish G (row 17 = warp 1, g==1, r0 path) ----
        if (w == 1 && g == 1) {
            slot[u % 3][bA] = Gc[0] + mtA + lg2(y0);
            slot[u % 3][bB] = Gc[1] + mtA + lg2(y1);
        }

        // ---- save boundary y/Gc for deferred processing ----
        if ((u % 7) == 6) {
            py[0] = y0; py[1] = y1; py[2] = y2; py[3] = y3;
            pG[0] = Gc[0]; pG[1] = Gc[1];
        }

        __syncthreads();
        Gc[0] = Gn0; Gc[1] = Gn1;
#pragma unroll
        for (int i = 0; i < 4; i++) { fcur[i] = fnx[i]; fnx[i] = fnew[i]; }
    }

    // ---- terminal boundary e = 15 (saved at u = 111) ----
    {
        float sA = fmaf(py[0], etlA, py[2] * etlB);
        float sB = fmaf(py[1], etlA, py[3] * etlB);
        sA += __shfl_xor_sync(0xffffffffu, sA, 4);
        sB += __shfl_xor_sync(0xffffffffu, sB, 4);
        sA += __shfl_xor_sync(0xffffffffu, sA, 8);
        sB += __shfl_xor_sync(0xffffffffu, sB, 8);
        sA += __shfl_xor_sync(0xffffffffu, sA, 16);
        sB += __shfl_xor_sync(0xffffffffu, sB, 16);
        if (lane < 4) {
            bwp[NEVT - 1][w][bA] = sA;
            bwp[NEVT - 1][w][bB] = sB;
            if (w == 0) { gsv[NEVT - 1][bA] = pG[0]; gsv[NEVT - 1][bB] = pG[1]; }
        }
    }
    __syncthreads();

    // ---- combine 16 events x 8 batches ----
    if (tid < 128) {
        int e = tid & 15, b = tid >> 4;
        float s8 = 0.0f;
#pragma unroll
        for (int ww = 0; ww < 8; ww++) s8 += bwp[e][ww][b];
        float val = gsv[e][b] + lg2(s8);
#pragma unroll
        for (int o = 1; o < 16; o <<= 1)
            val += __shfl_xor_sync(0xffffffffu, val, o);
        if (e == 0) g_partial[b0 + b] = val * LN2;
    }

    // ---- fused final reduction (last CTA) ----
    __threadfence();
    __syncthreads();
    if (tid == 0) {
        unsigned v = atomicAdd(&g_done, 1u);
        slast = (v == (unsigned)(nblocks - 1)) ? 1u : 0u;
    }
    __syncthreads();
    if (slast) {
        __threadfence();
        float v = __ldcg(&g_partial[tid]) + __ldcg(&g_partial[tid + 256]);
#pragma unroll
        for (int o = 16; o; o >>= 1) v += __shfl_xor_sync(0xffffffffu, v, o);
        if (lane == 0) rsum[w] = v;
        __syncthreads();
        if (tid == 0) {
            float tot = 0.0f;
#pragma unroll
            for (int ww = 0; ww < 8; ww++) tot += rsum[ww];
            out[0] = tot * (1.0f / (float)(BB * NEVT));
            g_done = 0;                 // restore for next graph replay
        }
    }
}

// ---------------------------------------------------------------------------
extern "C" void kernel_launch(void* const* d_in, const int* in_sizes, int n_in,
                              void* d_out, int out_size) {
    const float* feats = (const float*)d_in[0];
    const float* trans = (const float*)d_in[1];
    if (n_in >= 2 && in_sizes[0] == EE * EE) {   // defensive order check
        feats = (const float*)d_in[1];
        trans = (const float*)d_in[0];
    }
    crf_kernel<<<NBLK, 256>>>(feats, trans, (float*)d_out, NBLK);
}